// round 1
// baseline (speedup 1.0000x reference)
#include <cuda_runtime.h>
#include <cstdint>

// Problem constants (fixed by the reference)
#define N_NODES   100000
#define D         256
#define E_EDGES   1600000
#define NEG_SLOPE 0.01f

// Scratch: side = segment_sum(vals * ego[cols], rows)  [N, D] fp32 = 102.4 MB
__device__ float g_side[(size_t)N_NODES * D];

// ---------------------------------------------------------------------------
// Kernel 1: zero the side buffer (float4 stores, HBM write-bound)
// ---------------------------------------------------------------------------
__global__ void zero_side_kernel() {
    int i = blockIdx.x * blockDim.x + threadIdx.x;
    const int total4 = N_NODES * D / 4;  // 6.4M float4
    if (i < total4) {
        reinterpret_cast<float4*>(g_side)[i] = make_float4(0.f, 0.f, 0.f, 0.f);
    }
}

// ---------------------------------------------------------------------------
// Kernel 2: COO scatter. One warp per edge. Each lane moves two float4 chunks
// (32 lanes x 2 x 16B = 1KB row). Vector reduction red.global.add.v4.f32
// (sm_90+) -> 1 RED instruction per 16 bytes instead of 4 scalar atomics.
// Gather of ego[col] is 512B-contiguous per warp iteration (fully coalesced);
// ego table (100MB) lives in L2 after first touch.
// ---------------------------------------------------------------------------
__global__ __launch_bounds__(256) void scatter_kernel(
    const float* __restrict__ ego,
    const float* __restrict__ vals,
    const int*   __restrict__ rows,
    const int*   __restrict__ cols)
{
    int wid  = (blockIdx.x * blockDim.x + threadIdx.x) >> 5;
    int lane = threadIdx.x & 31;
    if (wid >= E_EDGES) return;

    const int   row = __ldg(rows + wid);
    const int   col = __ldg(cols + wid);
    const float v   = __ldg(vals + wid);

    const float4* __restrict__ src = reinterpret_cast<const float4*>(ego + (size_t)col * D);
    float* dst = g_side + (size_t)row * D;

#pragma unroll
    for (int it = 0; it < 2; it++) {
        int c = lane + it * 32;          // float4 chunk index, 0..63
        float4 m = __ldg(src + c);
        m.x *= v; m.y *= v; m.z *= v; m.w *= v;
        float* p = dst + c * 4;          // 16B-aligned (row base is 1KB-aligned)
        asm volatile(
            "red.global.add.v4.f32 [%0], {%1, %2, %3, %4};"
            :: "l"(p), "f"(m.x), "f"(m.y), "f"(m.z), "f"(m.w)
            : "memory");
    }
}

// ---------------------------------------------------------------------------
// Kernel 3: fused bi-interaction + dual GEMM + bias + LeakyReLU + sum.
//   out = LReLU((ego+side) @ W1 + b1) + LReLU((ego*side) @ W2 + b2)
// Classic smem-tiled fp32 GEMM: BM=64, BN=64, BK=16, 256 threads, each thread
// owns a 4x4 microtile for BOTH GEMMs (the ego/side tile load is shared).
// X tiles are stored k-major in smem so the inner loop broadcasts.
// ---------------------------------------------------------------------------
#define BM 64
#define BN 64
#define BK 16

__global__ __launch_bounds__(256) void gemm_fused_kernel(
    const float* __restrict__ ego,
    const float* __restrict__ W1, const float* __restrict__ b1,
    const float* __restrict__ W2, const float* __restrict__ b2,
    float* __restrict__ out)
{
    __shared__ float sX1[BK][BM + 4];   // (ego + side), k-major
    __shared__ float sX2[BK][BM + 4];   // (ego * side), k-major
    __shared__ float sW1[BK][BN + 4];
    __shared__ float sW2[BK][BN + 4];

    const int t    = threadIdx.x;
    const int tx   = t & 15;            // output-col group (4 cols each)
    const int ty   = t >> 4;            // output-row group (4 rows each)
    const int row0 = blockIdx.y * BM;
    const int col0 = blockIdx.x * BN;

    float acc1[4][4] = {};
    float acc2[4][4] = {};

    const int lkk = t & 15;             // k index this thread loads for X
    const int lr0 = t >> 4;             // base row this thread loads for X

    for (int k0 = 0; k0 < D; k0 += BK) {
        // --- load X tiles: 64 rows x 16 k, 4 rows per thread ---
#pragma unroll
        for (int i = 0; i < 4; i++) {
            int r    = lr0 + i * 16;
            int grow = row0 + r;
            float e = 0.f, s = 0.f;
            if (grow < N_NODES) {
                size_t off = (size_t)grow * D + k0 + lkk;
                e = __ldg(ego + off);
                s = g_side[off];
            }
            sX1[lkk][r] = e + s;
            sX2[lkk][r] = e * s;
        }
        // --- load W tiles: 16 k x 64 cols, 4 elems per thread, coalesced ---
#pragma unroll
        for (int i = 0; i < 4; i++) {
            int idx = t + i * 256;
            int wk  = idx >> 6;
            int c   = idx & 63;
            size_t off = (size_t)(k0 + wk) * D + col0 + c;
            sW1[wk][c] = __ldg(W1 + off);
            sW2[wk][c] = __ldg(W2 + off);
        }
        __syncthreads();

        // --- 4x4 microtile FMA for both GEMMs ---
#pragma unroll
        for (int kk = 0; kk < BK; kk++) {
            float a1[4], a2[4], w1v[4], w2v[4];
#pragma unroll
            for (int i = 0; i < 4; i++) {
                a1[i] = sX1[kk][ty * 4 + i];
                a2[i] = sX2[kk][ty * 4 + i];
            }
#pragma unroll
            for (int j = 0; j < 4; j++) {
                w1v[j] = sW1[kk][tx * 4 + j];
                w2v[j] = sW2[kk][tx * 4 + j];
            }
#pragma unroll
            for (int i = 0; i < 4; i++)
#pragma unroll
                for (int j = 0; j < 4; j++) {
                    acc1[i][j] = fmaf(a1[i], w1v[j], acc1[i][j]);
                    acc2[i][j] = fmaf(a2[i], w2v[j], acc2[i][j]);
                }
        }
        __syncthreads();
    }

    // --- epilogue: bias + LeakyReLU + sum, float4 stores ---
    float bb1[4], bb2[4];
#pragma unroll
    for (int j = 0; j < 4; j++) {
        bb1[j] = __ldg(b1 + col0 + tx * 4 + j);
        bb2[j] = __ldg(b2 + col0 + tx * 4 + j);
    }
#pragma unroll
    for (int i = 0; i < 4; i++) {
        int r = row0 + ty * 4 + i;
        if (r >= N_NODES) continue;
        float4 o;
        float res[4];
#pragma unroll
        for (int j = 0; j < 4; j++) {
            float o1 = acc1[i][j] + bb1[j];
            o1 = (o1 > 0.f) ? o1 : o1 * NEG_SLOPE;
            float o2 = acc2[i][j] + bb2[j];
            o2 = (o2 > 0.f) ? o2 : o2 * NEG_SLOPE;
            res[j] = o1 + o2;
        }
        o.x = res[0]; o.y = res[1]; o.z = res[2]; o.w = res[3];
        *reinterpret_cast<float4*>(out + (size_t)r * D + col0 + tx * 4) = o;
    }
}

// ---------------------------------------------------------------------------
// Launch. Input order (reference setup_inputs):
//   0 ego_embeddings [N*D] f32, 1 vals [E] f32, 2 W1 [D*D] f32, 3 b1 [D] f32,
//   4 W2 [D*D] f32, 5 b2 [D] f32, 6 rows [E] i32, 7 cols [E] i32
// Output: [N*D] f32.
// ---------------------------------------------------------------------------
extern "C" void kernel_launch(void* const* d_in, const int* in_sizes, int n_in,
                              void* d_out, int out_size)
{
    const float* ego  = (const float*)d_in[0];
    const float* vals = (const float*)d_in[1];
    const float* W1   = (const float*)d_in[2];
    const float* b1   = (const float*)d_in[3];
    const float* W2   = (const float*)d_in[4];
    const float* b2   = (const float*)d_in[5];
    const int*   rows = (const int*)d_in[6];
    const int*   cols = (const int*)d_in[7];
    float*       out  = (float*)d_out;

    // 1) zero side buffer
    {
        int total4 = N_NODES * D / 4;
        zero_side_kernel<<<(total4 + 255) / 256, 256>>>();
    }
    // 2) COO scatter: one warp per edge
    {
        long long threads = (long long)E_EDGES * 32;
        int blocks = (int)((threads + 255) / 256);
        scatter_kernel<<<blocks, 256>>>(ego, vals, rows, cols);
    }
    // 3) fused combine + dual GEMM
    {
        dim3 grid(D / BN, (N_NODES + BM - 1) / BM);  // (4, 1563)
        gemm_fused_kernel<<<grid, 256>>>(ego, W1, b1, W2, b2, out);
    }
}

// round 2
// speedup vs baseline: 1.1480x; 1.1480x over previous
#include <cuda_runtime.h>
#include <cstdint>

// Problem constants (fixed by the reference)
#define N_NODES   100000
#define D         256
#define E_EDGES   1600000
#define NEG_SLOPE 0.01f

// ---------------------------------------------------------------------------
// Device scratch (no allocs allowed):
//   g_side  : side = segment_sum(vals * ego[cols], rows)  [N, D] = 102.4 MB
//   CSR build: counts, start offsets, fill cursors, permuted (col,val)
// ---------------------------------------------------------------------------
__device__ float g_side[(size_t)N_NODES * D];
__device__ int   g_count[N_NODES];
__device__ int   g_start[N_NODES];
__device__ int   g_cursor[N_NODES];
__device__ int   g_ecol[E_EDGES];
__device__ float g_eval[E_EDGES];

// ---------------------------------------------------------------------------
// Kernel 1: zero the row-degree counters
// ---------------------------------------------------------------------------
__global__ void zero_counts_kernel() {
    int i = blockIdx.x * blockDim.x + threadIdx.x;
    if (i < N_NODES) g_count[i] = 0;
}

// ---------------------------------------------------------------------------
// Kernel 2: histogram of rows
// ---------------------------------------------------------------------------
__global__ __launch_bounds__(256) void hist_kernel(const int* __restrict__ rows) {
    int e = blockIdx.x * blockDim.x + threadIdx.x;
    if (e < E_EDGES) atomicAdd(&g_count[rows[e]], 1);
}

// ---------------------------------------------------------------------------
// Kernel 3: exclusive scan of counts -> start offsets (+ init cursors).
// Single block, 1024 threads, ~98 elements each, Hillis-Steele block scan.
// ---------------------------------------------------------------------------
#define SCAN_T 1024
#define CHUNK  ((N_NODES + SCAN_T - 1) / SCAN_T)   // 98

__global__ __launch_bounds__(SCAN_T) void scan_kernel() {
    __shared__ int ssum[SCAN_T];
    const int t = threadIdx.x;
    const int base = t * CHUNK;
    int s = 0;
#pragma unroll 4
    for (int i = 0; i < CHUNK; i++) {
        int idx = base + i;
        if (idx < N_NODES) s += g_count[idx];
    }
    ssum[t] = s;
    __syncthreads();
    // inclusive scan over thread totals
    for (int off = 1; off < SCAN_T; off <<= 1) {
        int v = (t >= off) ? ssum[t - off] : 0;
        __syncthreads();
        ssum[t] += v;
        __syncthreads();
    }
    int run = ssum[t] - s;   // exclusive prefix for this thread's chunk
#pragma unroll 4
    for (int i = 0; i < CHUNK; i++) {
        int idx = base + i;
        if (idx < N_NODES) {
            int c = g_count[idx];
            g_start[idx]  = run;
            g_cursor[idx] = run;
            run += c;
        }
    }
}

// ---------------------------------------------------------------------------
// Kernel 4: permute (col, val) into row-sorted CSR order
// ---------------------------------------------------------------------------
__global__ __launch_bounds__(256) void fill_kernel(
    const int* __restrict__ rows, const int* __restrict__ cols,
    const float* __restrict__ vals)
{
    int e = blockIdx.x * blockDim.x + threadIdx.x;
    if (e >= E_EDGES) return;
    int r = rows[e];
    int pos = atomicAdd(&g_cursor[r], 1);
    g_ecol[pos] = cols[e];
    g_eval[pos] = vals[e];
}

// ---------------------------------------------------------------------------
// Kernel 5: CSR SpMM, one warp per row. Each lane owns 8 floats (2 float4)
// of the 256-wide row in registers; loop over the row's edges gathering
// ego[col] (1KB coalesced per edge, L2-resident), FMA, then one streaming
// 1KB store of side[row]. No atomics anywhere.
// ---------------------------------------------------------------------------
__global__ __launch_bounds__(256) void spmm_kernel(const float* __restrict__ ego)
{
    int wid  = (blockIdx.x * blockDim.x + threadIdx.x) >> 5;
    int lane = threadIdx.x & 31;
    if (wid >= N_NODES) return;

    const int start = g_start[wid];
    const int cnt   = g_count[wid];

    const float4* __restrict__ ego4 = reinterpret_cast<const float4*>(ego);
    float4 acc0 = make_float4(0.f, 0.f, 0.f, 0.f);
    float4 acc1 = make_float4(0.f, 0.f, 0.f, 0.f);

    int e = start;
    const int end = start + cnt;
    // unroll by 2 for MLP
    for (; e + 1 < end; e += 2) {
        int   c0 = g_ecol[e],     c1 = g_ecol[e + 1];
        float v0 = g_eval[e],     v1 = g_eval[e + 1];
        float4 a0 = __ldg(ego4 + (size_t)c0 * 64 + lane);
        float4 b0 = __ldg(ego4 + (size_t)c0 * 64 + lane + 32);
        float4 a1 = __ldg(ego4 + (size_t)c1 * 64 + lane);
        float4 b1 = __ldg(ego4 + (size_t)c1 * 64 + lane + 32);
        acc0.x = fmaf(v0, a0.x, acc0.x); acc0.y = fmaf(v0, a0.y, acc0.y);
        acc0.z = fmaf(v0, a0.z, acc0.z); acc0.w = fmaf(v0, a0.w, acc0.w);
        acc1.x = fmaf(v0, b0.x, acc1.x); acc1.y = fmaf(v0, b0.y, acc1.y);
        acc1.z = fmaf(v0, b0.z, acc1.z); acc1.w = fmaf(v0, b0.w, acc1.w);
        acc0.x = fmaf(v1, a1.x, acc0.x); acc0.y = fmaf(v1, a1.y, acc0.y);
        acc0.z = fmaf(v1, a1.z, acc0.z); acc0.w = fmaf(v1, a1.w, acc0.w);
        acc1.x = fmaf(v1, b1.x, acc1.x); acc1.y = fmaf(v1, b1.y, acc1.y);
        acc1.z = fmaf(v1, b1.z, acc1.z); acc1.w = fmaf(v1, b1.w, acc1.w);
    }
    if (e < end) {
        int   c0 = g_ecol[e];
        float v0 = g_eval[e];
        float4 a0 = __ldg(ego4 + (size_t)c0 * 64 + lane);
        float4 b0 = __ldg(ego4 + (size_t)c0 * 64 + lane + 32);
        acc0.x = fmaf(v0, a0.x, acc0.x); acc0.y = fmaf(v0, a0.y, acc0.y);
        acc0.z = fmaf(v0, a0.z, acc0.z); acc0.w = fmaf(v0, a0.w, acc0.w);
        acc1.x = fmaf(v0, b0.x, acc1.x); acc1.y = fmaf(v0, b0.y, acc1.y);
        acc1.z = fmaf(v0, b0.z, acc1.z); acc1.w = fmaf(v0, b0.w, acc1.w);
    }

    float4* side4 = reinterpret_cast<float4*>(g_side) + (size_t)wid * 64;
    side4[lane]      = acc0;
    side4[lane + 32] = acc1;
}

// ---------------------------------------------------------------------------
// Kernel 6: fused bi-interaction + dual GEMM + bias + LeakyReLU + sum.
//   out = LReLU((ego+side) @ W1 + b1) + LReLU((ego*side) @ W2 + b2)
// BM=BN=128, BK=16, 256 threads, 8x8 microtile per thread for BOTH GEMMs.
// Per k-step per thread: 32 shared floats -> 128 FMAs (LDS:FMA = 1:1).
// ---------------------------------------------------------------------------
#define BM 128
#define BN 128
#define BK 16

__global__ __launch_bounds__(256) void gemm_fused_kernel(
    const float* __restrict__ ego,
    const float* __restrict__ W1, const float* __restrict__ b1,
    const float* __restrict__ W2, const float* __restrict__ b2,
    float* __restrict__ out)
{
    __shared__ float sX1[BK][BM + 4];   // (ego + side), k-major
    __shared__ float sX2[BK][BM + 4];   // (ego * side), k-major
    __shared__ float sW1[BK][BN + 4];
    __shared__ float sW2[BK][BN + 4];

    const int t    = threadIdx.x;
    const int tx   = t & 15;            // col group (8 cols)
    const int ty   = t >> 4;            // row group (8 rows)
    const int row0 = blockIdx.y * BM;
    const int col0 = blockIdx.x * BN;

    float acc1[8][8] = {};
    float acc2[8][8] = {};

    const int lkk = t & 15;             // k index this thread loads for X
    const int lr0 = t >> 4;             // base row this thread loads for X

    for (int k0 = 0; k0 < D; k0 += BK) {
        // --- X tiles: 128 rows x 16 k, 8 rows per thread ---
#pragma unroll
        for (int i = 0; i < 8; i++) {
            int r    = lr0 + i * 16;
            int grow = row0 + r;
            float e = 0.f, s = 0.f;
            if (grow < N_NODES) {
                size_t off = (size_t)grow * D + k0 + lkk;
                e = __ldg(ego + off);
                s = g_side[off];
            }
            sX1[lkk][r] = e + s;
            sX2[lkk][r] = e * s;
        }
        // --- W tiles: 16 k x 128 cols, float4 loads, 2 per thread per W ---
#pragma unroll
        for (int i = 0; i < 2; i++) {
            int idx = t + i * 256;      // 0..511 float4 slots
            int wk  = idx >> 5;         // 32 float4 per k-row
            int c4  = idx & 31;
            size_t off4 = ((size_t)(k0 + wk) * D + col0) / 4 + c4;
            float4 w1v = __ldg(reinterpret_cast<const float4*>(W1) + off4);
            float4 w2v = __ldg(reinterpret_cast<const float4*>(W2) + off4);
            *reinterpret_cast<float4*>(&sW1[wk][c4 * 4]) = w1v;
            *reinterpret_cast<float4*>(&sW2[wk][c4 * 4]) = w2v;
        }
        __syncthreads();

        // --- 8x8 microtile FMA for both GEMMs ---
#pragma unroll
        for (int kk = 0; kk < BK; kk++) {
            float a1[8], a2[8], w1r[8], w2r[8];
#pragma unroll
            for (int i = 0; i < 8; i++) {
                a1[i] = sX1[kk][ty * 8 + i];
                a2[i] = sX2[kk][ty * 8 + i];
            }
#pragma unroll
            for (int j = 0; j < 8; j++) {
                w1r[j] = sW1[kk][tx * 8 + j];
                w2r[j] = sW2[kk][tx * 8 + j];
            }
#pragma unroll
            for (int i = 0; i < 8; i++)
#pragma unroll
                for (int j = 0; j < 8; j++) {
                    acc1[i][j] = fmaf(a1[i], w1r[j], acc1[i][j]);
                    acc2[i][j] = fmaf(a2[i], w2r[j], acc2[i][j]);
                }
        }
        __syncthreads();
    }

    // --- epilogue: bias + LeakyReLU + sum, two float4 stores per row ---
    float bb1[8], bb2[8];
#pragma unroll
    for (int j = 0; j < 8; j++) {
        bb1[j] = __ldg(b1 + col0 + tx * 8 + j);
        bb2[j] = __ldg(b2 + col0 + tx * 8 + j);
    }
#pragma unroll
    for (int i = 0; i < 8; i++) {
        int r = row0 + ty * 8 + i;
        if (r >= N_NODES) continue;
        float res[8];
#pragma unroll
        for (int j = 0; j < 8; j++) {
            float o1 = acc1[i][j] + bb1[j];
            o1 = (o1 > 0.f) ? o1 : o1 * NEG_SLOPE;
            float o2 = acc2[i][j] + bb2[j];
            o2 = (o2 > 0.f) ? o2 : o2 * NEG_SLOPE;
            res[j] = o1 + o2;
        }
        float* op = out + (size_t)r * D + col0 + tx * 8;
        *reinterpret_cast<float4*>(op)     = make_float4(res[0], res[1], res[2], res[3]);
        *reinterpret_cast<float4*>(op + 4) = make_float4(res[4], res[5], res[6], res[7]);
    }
}

// ---------------------------------------------------------------------------
// Launch. Input order (reference setup_inputs):
//   0 ego [N*D] f32, 1 vals [E] f32, 2 W1 [D*D] f32, 3 b1 [D] f32,
//   4 W2 [D*D] f32, 5 b2 [D] f32, 6 rows [E] i32, 7 cols [E] i32
// ---------------------------------------------------------------------------
extern "C" void kernel_launch(void* const* d_in, const int* in_sizes, int n_in,
                              void* d_out, int out_size)
{
    const float* ego  = (const float*)d_in[0];
    const float* vals = (const float*)d_in[1];
    const float* W1   = (const float*)d_in[2];
    const float* b1   = (const float*)d_in[3];
    const float* W2   = (const float*)d_in[4];
    const float* b2   = (const float*)d_in[5];
    const int*   rows = (const int*)d_in[6];
    const int*   cols = (const int*)d_in[7];
    float*       out  = (float*)d_out;

    // 1) zero degree counters
    zero_counts_kernel<<<(N_NODES + 255) / 256, 256>>>();
    // 2) row histogram
    hist_kernel<<<(E_EDGES + 255) / 256, 256>>>(rows);
    // 3) offsets scan
    scan_kernel<<<1, SCAN_T>>>();
    // 4) CSR fill (permute edges by row)
    fill_kernel<<<(E_EDGES + 255) / 256, 256>>>(rows, cols, vals);
    // 5) SpMM: one warp per row
    {
        long long threads = (long long)N_NODES * 32;
        int blocks = (int)((threads + 255) / 256);
        spmm_kernel<<<blocks, 256>>>(ego);
    }
    // 6) fused combine + dual GEMM
    {
        dim3 grid(D / BN, (N_NODES + BM - 1) / BM);  // (2, 782)
        gemm_fused_kernel<<<grid, 256>>>(ego, W1, b1, W2, b2, out);
    }
}

// round 4
// speedup vs baseline: 1.7776x; 1.5484x over previous
#include <cuda_runtime.h>
#include <cstdint>

// Problem constants (fixed by the reference)
#define N_NODES   100000
#define D         256
#define E_EDGES   1600000
#define NEG_SLOPE 0.01f

// ---------------------------------------------------------------------------
// Device scratch (no allocs allowed)
// ---------------------------------------------------------------------------
__device__ float g_side[(size_t)N_NODES * D];   // 102.4 MB
__device__ int   g_count[N_NODES];
__device__ int   g_start[N_NODES];
__device__ int   g_cursor[N_NODES];
__device__ int   g_ecol[E_EDGES];
__device__ float g_eval[E_EDGES];

// ---------------------------------------------------------------------------
// Kernel 1: zero the row-degree counters
// ---------------------------------------------------------------------------
__global__ void zero_counts_kernel() {
    int i = blockIdx.x * blockDim.x + threadIdx.x;
    if (i < N_NODES) g_count[i] = 0;
}

// ---------------------------------------------------------------------------
// Kernel 2: histogram of rows
// ---------------------------------------------------------------------------
__global__ __launch_bounds__(256) void hist_kernel(const int* __restrict__ rows) {
    int e = blockIdx.x * blockDim.x + threadIdx.x;
    if (e < E_EDGES) atomicAdd(&g_count[rows[e]], 1);
}

// ---------------------------------------------------------------------------
// Kernel 3: exclusive scan of counts -> start offsets (+ init cursors)
// ---------------------------------------------------------------------------
#define SCAN_T 1024
#define CHUNK  ((N_NODES + SCAN_T - 1) / SCAN_T)   // 98

__global__ __launch_bounds__(SCAN_T) void scan_kernel() {
    __shared__ int ssum[SCAN_T];
    const int t = threadIdx.x;
    const int base = t * CHUNK;
    int s = 0;
#pragma unroll 4
    for (int i = 0; i < CHUNK; i++) {
        int idx = base + i;
        if (idx < N_NODES) s += g_count[idx];
    }
    ssum[t] = s;
    __syncthreads();
    for (int off = 1; off < SCAN_T; off <<= 1) {
        int v = (t >= off) ? ssum[t - off] : 0;
        __syncthreads();
        ssum[t] += v;
        __syncthreads();
    }
    int run = ssum[t] - s;
#pragma unroll 4
    for (int i = 0; i < CHUNK; i++) {
        int idx = base + i;
        if (idx < N_NODES) {
            int c = g_count[idx];
            g_start[idx]  = run;
            g_cursor[idx] = run;
            run += c;
        }
    }
}

// ---------------------------------------------------------------------------
// Kernel 4: permute (col, val) into row-sorted CSR order
// ---------------------------------------------------------------------------
__global__ __launch_bounds__(256) void fill_kernel(
    const int* __restrict__ rows, const int* __restrict__ cols,
    const float* __restrict__ vals)
{
    int e = blockIdx.x * blockDim.x + threadIdx.x;
    if (e >= E_EDGES) return;
    int r = rows[e];
    int pos = atomicAdd(&g_cursor[r], 1);
    g_ecol[pos] = cols[e];
    g_eval[pos] = vals[e];
}

// ---------------------------------------------------------------------------
// Kernel 5: CSR SpMM, one warp per row, unroll 4 (8 float4 gathers in flight)
// ---------------------------------------------------------------------------
__device__ __forceinline__ void fma4(float4& acc, float v, const float4& a) {
    acc.x = fmaf(v, a.x, acc.x); acc.y = fmaf(v, a.y, acc.y);
    acc.z = fmaf(v, a.z, acc.z); acc.w = fmaf(v, a.w, acc.w);
}

__global__ __launch_bounds__(256) void spmm_kernel(const float* __restrict__ ego)
{
    int wid  = (blockIdx.x * blockDim.x + threadIdx.x) >> 5;
    int lane = threadIdx.x & 31;
    if (wid >= N_NODES) return;

    const int start = g_start[wid];
    const int end   = start + g_count[wid];

    const float4* __restrict__ ego4 = reinterpret_cast<const float4*>(ego);
    float4 acc0 = make_float4(0.f, 0.f, 0.f, 0.f);
    float4 acc1 = make_float4(0.f, 0.f, 0.f, 0.f);

    int e = start;
    for (; e + 3 < end; e += 4) {
        int   c0 = g_ecol[e],   c1 = g_ecol[e+1], c2 = g_ecol[e+2], c3 = g_ecol[e+3];
        float v0 = g_eval[e],   v1 = g_eval[e+1], v2 = g_eval[e+2], v3 = g_eval[e+3];
        float4 a0 = __ldg(ego4 + (size_t)c0 * 64 + lane);
        float4 b0 = __ldg(ego4 + (size_t)c0 * 64 + lane + 32);
        float4 a1 = __ldg(ego4 + (size_t)c1 * 64 + lane);
        float4 b1 = __ldg(ego4 + (size_t)c1 * 64 + lane + 32);
        float4 a2 = __ldg(ego4 + (size_t)c2 * 64 + lane);
        float4 b2 = __ldg(ego4 + (size_t)c2 * 64 + lane + 32);
        float4 a3 = __ldg(ego4 + (size_t)c3 * 64 + lane);
        float4 b3 = __ldg(ego4 + (size_t)c3 * 64 + lane + 32);
        fma4(acc0, v0, a0); fma4(acc1, v0, b0);
        fma4(acc0, v1, a1); fma4(acc1, v1, b1);
        fma4(acc0, v2, a2); fma4(acc1, v2, b2);
        fma4(acc0, v3, a3); fma4(acc1, v3, b3);
    }
    for (; e < end; e++) {
        int   c0 = g_ecol[e];
        float v0 = g_eval[e];
        float4 a0 = __ldg(ego4 + (size_t)c0 * 64 + lane);
        float4 b0 = __ldg(ego4 + (size_t)c0 * 64 + lane + 32);
        fma4(acc0, v0, a0); fma4(acc1, v0, b0);
    }

    float4* side4 = reinterpret_cast<float4*>(g_side) + (size_t)wid * 64;
    side4[lane]      = acc0;
    side4[lane + 32] = acc1;
}

// ---------------------------------------------------------------------------
// Kernel 6: fused bi-interaction + dual GEMM (TF32 tensor cores)
//   out = LReLU((ego+side) @ W1 + b1) + LReLU((ego*side) @ W2 + b2)
// BM=128, BN=128, BK=16. 8 warps as 2(M)x4(N); warp tile 64x32 per GEMM.
// mma.sync.m16n8k8 tf32, fp32 accumulate. Inputs tf32-rounded at smem fill.
// Register prefetch double-buffers the global loads across BK iterations.
// ---------------------------------------------------------------------------
#define BM 128
#define BN 128
#define BK 16
#define XPAD 4     // A row stride 20 words -> conflict-free fragment LDS
#define WPAD 8     // B row stride 136 words -> conflict-free fragment LDS

__device__ __forceinline__ uint32_t f2tf32(float x) {
    uint32_t r;
    asm("cvt.rna.tf32.f32 %0, %1;" : "=r"(r) : "f"(x));
    return r;
}

__device__ __forceinline__ void mma_tf32(float* c, const uint32_t* a,
                                         uint32_t b0, uint32_t b1) {
    asm volatile(
        "mma.sync.aligned.m16n8k8.row.col.f32.tf32.tf32.f32 "
        "{%0,%1,%2,%3}, {%4,%5,%6,%7}, {%8,%9}, {%0,%1,%2,%3};\n"
        : "+f"(c[0]), "+f"(c[1]), "+f"(c[2]), "+f"(c[3])
        : "r"(a[0]), "r"(a[1]), "r"(a[2]), "r"(a[3]), "r"(b0), "r"(b1));
}

__global__ __launch_bounds__(256) void gemm_tc_kernel(
    const float* __restrict__ ego,
    const float* __restrict__ W1, const float* __restrict__ b1,
    const float* __restrict__ W2, const float* __restrict__ b2,
    float* __restrict__ out)
{
    __shared__ uint32_t sX1[BM][BK + XPAD];
    __shared__ uint32_t sX2[BM][BK + XPAD];
    __shared__ uint32_t sW1[BK][BN + WPAD];
    __shared__ uint32_t sW2[BK][BN + WPAD];

    const int t      = threadIdx.x;
    const int lane   = t & 31;
    const int wid    = t >> 5;
    const int warp_m = wid & 1;         // 0..1 (64-row band)
    const int warp_n = wid >> 1;        // 0..3 (32-col band)
    const int row0   = blockIdx.y * BM;
    const int col0   = blockIdx.x * BN;
    const int tg     = lane & 3;        // threadID in group
    const int gid    = lane >> 2;       // groupID

    float c1[4][4][4] = {};
    float c2[4][4][4] = {};

    // ----- global-load assignments -----
    // X: 2 passes; pass p loads row (p*64 + t/4), k-chunk (t%4)*4 (float4)
    const int xrow = t >> 2;            // 0..63
    const int xk4  = (t & 3) * 4;       // 0,4,8,12
    float4 pe[2], ps[2], pw1[2], pw2[2];

    auto load_tiles = [&](int k0) {
#pragma unroll
        for (int p = 0; p < 2; p++) {
            int grow = row0 + p * 64 + xrow;
            if (grow < N_NODES) {
                size_t off4 = ((size_t)grow * D + k0 + xk4) >> 2;
                pe[p] = __ldg(reinterpret_cast<const float4*>(ego) + off4);
                ps[p] = *(reinterpret_cast<const float4*>(g_side) + off4);
            } else {
                pe[p] = make_float4(0.f, 0.f, 0.f, 0.f);
                ps[p] = make_float4(0.f, 0.f, 0.f, 0.f);
            }
        }
#pragma unroll
        for (int i = 0; i < 2; i++) {
            int slot = t + i * 256;     // 0..511
            int wk   = slot >> 5;       // 0..15
            int c4   = (slot & 31) * 4; // 0..124
            size_t off4 = ((size_t)(k0 + wk) * D + col0 + c4) >> 2;
            pw1[i] = __ldg(reinterpret_cast<const float4*>(W1) + off4);
            pw2[i] = __ldg(reinterpret_cast<const float4*>(W2) + off4);
        }
    };

    auto store_tiles = [&]() {
#pragma unroll
        for (int p = 0; p < 2; p++) {
            int r = p * 64 + xrow;
            const float* e = &pe[p].x;
            const float* s = &ps[p].x;
#pragma unroll
            for (int j = 0; j < 4; j++) {
                sX1[r][xk4 + j] = f2tf32(e[j] + s[j]);
                sX2[r][xk4 + j] = f2tf32(e[j] * s[j]);
            }
        }
#pragma unroll
        for (int i = 0; i < 2; i++) {
            int slot = t + i * 256;
            int wk   = slot >> 5;
            int c4   = (slot & 31) * 4;
            const float* w1 = &pw1[i].x;
            const float* w2 = &pw2[i].x;
#pragma unroll
            for (int j = 0; j < 4; j++) {
                sW1[wk][c4 + j] = f2tf32(w1[j]);
                sW2[wk][c4 + j] = f2tf32(w2[j]);
            }
        }
    };

    load_tiles(0);

    const int NITER = D / BK;           // 16
    for (int it = 0; it < NITER; it++) {
        store_tiles();
        __syncthreads();
        if (it + 1 < NITER) load_tiles((it + 1) * BK);

        // ----- compute 2 k8 steps from smem -----
#pragma unroll
        for (int ks = 0; ks < 2; ks++) {
            const int k8 = ks * 8;
            // --- GEMM 1 ---
            {
                uint32_t a[4][4];
#pragma unroll
                for (int mt = 0; mt < 4; mt++) {
                    int r = warp_m * 64 + mt * 16 + gid;
                    int c = k8 + tg;
                    a[mt][0] = sX1[r][c];
                    a[mt][1] = sX1[r + 8][c];
                    a[mt][2] = sX1[r][c + 4];
                    a[mt][3] = sX1[r + 8][c + 4];
                }
#pragma unroll
                for (int nt = 0; nt < 4; nt++) {
                    int n = warp_n * 32 + nt * 8 + gid;
                    int k = k8 + tg;
                    uint32_t b0 = sW1[k][n];
                    uint32_t b1v = sW1[k + 4][n];
#pragma unroll
                    for (int mt = 0; mt < 4; mt++)
                        mma_tf32(c1[mt][nt], a[mt], b0, b1v);
                }
            }
            // --- GEMM 2 ---
            {
                uint32_t a[4][4];
#pragma unroll
                for (int mt = 0; mt < 4; mt++) {
                    int r = warp_m * 64 + mt * 16 + gid;
                    int c = k8 + tg;
                    a[mt][0] = sX2[r][c];
                    a[mt][1] = sX2[r + 8][c];
                    a[mt][2] = sX2[r][c + 4];
                    a[mt][3] = sX2[r + 8][c + 4];
                }
#pragma unroll
                for (int nt = 0; nt < 4; nt++) {
                    int n = warp_n * 32 + nt * 8 + gid;
                    int k = k8 + tg;
                    uint32_t b0 = sW2[k][n];
                    uint32_t b1v = sW2[k + 4][n];
#pragma unroll
                    for (int mt = 0; mt < 4; mt++)
                        mma_tf32(c2[mt][nt], a[mt], b0, b1v);
                }
            }
        }
        __syncthreads();
    }

    // ----- epilogue: bias + LeakyReLU + sum -----
#pragma unroll
    for (int nt = 0; nt < 4; nt++) {
        int col = col0 + warp_n * 32 + nt * 8 + 2 * tg;
        float bb1_0 = __ldg(b1 + col),     bb1_1 = __ldg(b1 + col + 1);
        float bb2_0 = __ldg(b2 + col),     bb2_1 = __ldg(b2 + col + 1);
#pragma unroll
        for (int mt = 0; mt < 4; mt++) {
            int r = row0 + warp_m * 64 + mt * 16 + gid;
            float* cc1 = c1[mt][nt];
            float* cc2 = c2[mt][nt];
            if (r < N_NODES) {
                float o1a = cc1[0] + bb1_0; o1a = (o1a > 0.f) ? o1a : o1a * NEG_SLOPE;
                float o1b = cc1[1] + bb1_1; o1b = (o1b > 0.f) ? o1b : o1b * NEG_SLOPE;
                float o2a = cc2[0] + bb2_0; o2a = (o2a > 0.f) ? o2a : o2a * NEG_SLOPE;
                float o2b = cc2[1] + bb2_1; o2b = (o2b > 0.f) ? o2b : o2b * NEG_SLOPE;
                *reinterpret_cast<float2*>(out + (size_t)r * D + col) =
                    make_float2(o1a + o2a, o1b + o2b);
            }
            int r8 = r + 8;
            if (r8 < N_NODES) {
                float o1a = cc1[2] + bb1_0; o1a = (o1a > 0.f) ? o1a : o1a * NEG_SLOPE;
                float o1b = cc1[3] + bb1_1; o1b = (o1b > 0.f) ? o1b : o1b * NEG_SLOPE;
                float o2a = cc2[2] + bb2_0; o2a = (o2a > 0.f) ? o2a : o2a * NEG_SLOPE;
                float o2b = cc2[3] + bb2_1; o2b = (o2b > 0.f) ? o2b : o2b * NEG_SLOPE;
                *reinterpret_cast<float2*>(out + (size_t)r8 * D + col) =
                    make_float2(o1a + o2a, o1b + o2b);
            }
        }
    }
}

// ---------------------------------------------------------------------------
// Launch. Input order: 0 ego, 1 vals, 2 W1, 3 b1, 4 W2, 5 b2, 6 rows, 7 cols
// ---------------------------------------------------------------------------
extern "C" void kernel_launch(void* const* d_in, const int* in_sizes, int n_in,
                              void* d_out, int out_size)
{
    const float* ego  = (const float*)d_in[0];
    const float* vals = (const float*)d_in[1];
    const float* W1   = (const float*)d_in[2];
    const float* b1   = (const float*)d_in[3];
    const float* W2   = (const float*)d_in[4];
    const float* b2   = (const float*)d_in[5];
    const int*   rows = (const int*)d_in[6];
    const int*   cols = (const int*)d_in[7];
    float*       out  = (float*)d_out;

    zero_counts_kernel<<<(N_NODES + 255) / 256, 256>>>();
    hist_kernel<<<(E_EDGES + 255) / 256, 256>>>(rows);
    scan_kernel<<<1, SCAN_T>>>();
    fill_kernel<<<(E_EDGES + 255) / 256, 256>>>(rows, cols, vals);
    {
        long long threads = (long long)N_NODES * 32;
        int blocks = (int)((threads + 255) / 256);
        spmm_kernel<<<blocks, 256>>>(ego);
    }
    {
        dim3 grid(D / BN, (N_NODES + BM - 1) / BM);  // (2, 782)
        gemm_tc_kernel<<<grid, 256>>>(ego, W1, b1, W2, b2, out);
    }
}

// round 5
// speedup vs baseline: 1.8678x; 1.0508x over previous
#include <cuda_runtime.h>
#include <cstdint>

// Problem constants (fixed by the reference)
#define N_NODES   100000
#define D         256
#define E_EDGES   1600000
#define NEG_SLOPE 0.01f

// ---------------------------------------------------------------------------
// Device scratch (no allocs allowed)
// ---------------------------------------------------------------------------
__device__ float g_side[(size_t)N_NODES * D];   // 102.4 MB
__device__ int   g_count[N_NODES];
__device__ int   g_start[N_NODES];
__device__ int   g_cursor[N_NODES];
__device__ int   g_ecol[E_EDGES];
__device__ float g_eval[E_EDGES];

// ---------------------------------------------------------------------------
// Kernel 1: zero the row-degree counters
// ---------------------------------------------------------------------------
__global__ void zero_counts_kernel() {
    int i = blockIdx.x * blockDim.x + threadIdx.x;
    if (i < N_NODES) g_count[i] = 0;
}

// ---------------------------------------------------------------------------
// Kernel 2: histogram of rows
// ---------------------------------------------------------------------------
__global__ __launch_bounds__(256) void hist_kernel(const int* __restrict__ rows) {
    int e = blockIdx.x * blockDim.x + threadIdx.x;
    if (e < E_EDGES) atomicAdd(&g_count[rows[e]], 1);
}

// ---------------------------------------------------------------------------
// Kernel 3: exclusive scan of counts -> start offsets (+ init cursors)
// ---------------------------------------------------------------------------
#define SCAN_T 1024
#define CHUNK  ((N_NODES + SCAN_T - 1) / SCAN_T)   // 98

__global__ __launch_bounds__(SCAN_T) void scan_kernel() {
    __shared__ int ssum[SCAN_T];
    const int t = threadIdx.x;
    const int base = t * CHUNK;
    int s = 0;
#pragma unroll 4
    for (int i = 0; i < CHUNK; i++) {
        int idx = base + i;
        if (idx < N_NODES) s += g_count[idx];
    }
    ssum[t] = s;
    __syncthreads();
    for (int off = 1; off < SCAN_T; off <<= 1) {
        int v = (t >= off) ? ssum[t - off] : 0;
        __syncthreads();
        ssum[t] += v;
        __syncthreads();
    }
    int run = ssum[t] - s;
#pragma unroll 4
    for (int i = 0; i < CHUNK; i++) {
        int idx = base + i;
        if (idx < N_NODES) {
            int c = g_count[idx];
            g_start[idx]  = run;
            g_cursor[idx] = run;
            run += c;
        }
    }
}

// ---------------------------------------------------------------------------
// Kernel 4: permute (col, val) into row-sorted CSR order
// ---------------------------------------------------------------------------
__global__ __launch_bounds__(256) void fill_kernel(
    const int* __restrict__ rows, const int* __restrict__ cols,
    const float* __restrict__ vals)
{
    int e = blockIdx.x * blockDim.x + threadIdx.x;
    if (e >= E_EDGES) return;
    int r = rows[e];
    int pos = atomicAdd(&g_cursor[r], 1);
    g_ecol[pos] = cols[e];
    g_eval[pos] = vals[e];
}

// ---------------------------------------------------------------------------
// Kernel 5: CSR SpMM, feature-split for L2 residency.
// One warp per row; each launch covers 128 of 256 features (c4off in float4
// units: 0 or 32). Per pass the gather source ego[:, half] is 50 MB ->
// L2-resident, so the 800 MB of logical gather traffic per pass is served
// from L2 at the LTS cap instead of HBM. Unroll 8 => 8 independent float4
// gathers in flight per lane.
// ---------------------------------------------------------------------------
__device__ __forceinline__ void fma4(float4& acc, float v, const float4& a) {
    acc.x = fmaf(v, a.x, acc.x); acc.y = fmaf(v, a.y, acc.y);
    acc.z = fmaf(v, a.z, acc.z); acc.w = fmaf(v, a.w, acc.w);
}

__global__ __launch_bounds__(256) void spmm_half_kernel(
    const float* __restrict__ ego, int c4off)
{
    int wid  = (blockIdx.x * blockDim.x + threadIdx.x) >> 5;
    int lane = threadIdx.x & 31;
    if (wid >= N_NODES) return;

    const int start = g_start[wid];
    const int end   = start + g_count[wid];
    const int c4    = c4off + lane;     // this lane's float4 column

    const float4* __restrict__ ego4 = reinterpret_cast<const float4*>(ego);
    float4 acc = make_float4(0.f, 0.f, 0.f, 0.f);

    int e = start;
    for (; e + 7 < end; e += 8) {
        int   c[8]; float v[8]; float4 a[8];
#pragma unroll
        for (int i = 0; i < 8; i++) { c[i] = g_ecol[e + i]; v[i] = g_eval[e + i]; }
#pragma unroll
        for (int i = 0; i < 8; i++) a[i] = __ldg(ego4 + (size_t)c[i] * 64 + c4);
#pragma unroll
        for (int i = 0; i < 8; i++) fma4(acc, v[i], a[i]);
    }
    for (; e < end; e++) {
        int   cc = g_ecol[e];
        float vv = g_eval[e];
        float4 aa = __ldg(ego4 + (size_t)cc * 64 + c4);
        fma4(acc, vv, aa);
    }

    reinterpret_cast<float4*>(g_side)[(size_t)wid * 64 + c4] = acc;
}

// ---------------------------------------------------------------------------
// Kernel 6: fused bi-interaction + dual GEMM (TF32 tensor cores)
//   out = LReLU((ego+side) @ W1 + b1) + LReLU((ego*side) @ W2 + b2)
// BM=128, BN=128, BK=16. 8 warps as 2(M)x4(N); warp tile 64x32 per GEMM.
// mma.sync.m16n8k8 tf32, fp32 accumulate. Inputs tf32-rounded at smem fill.
// Register prefetch double-buffers the global loads across BK iterations.
// ---------------------------------------------------------------------------
#define BM 128
#define BN 128
#define BK 16
#define XPAD 4     // A row stride 20 words -> conflict-free fragment LDS
#define WPAD 8     // B row stride 136 words -> conflict-free fragment LDS

__device__ __forceinline__ uint32_t f2tf32(float x) {
    uint32_t r;
    asm("cvt.rna.tf32.f32 %0, %1;" : "=r"(r) : "f"(x));
    return r;
}

__device__ __forceinline__ void mma_tf32(float* c, const uint32_t* a,
                                         uint32_t b0, uint32_t b1) {
    asm volatile(
        "mma.sync.aligned.m16n8k8.row.col.f32.tf32.tf32.f32 "
        "{%0,%1,%2,%3}, {%4,%5,%6,%7}, {%8,%9}, {%0,%1,%2,%3};\n"
        : "+f"(c[0]), "+f"(c[1]), "+f"(c[2]), "+f"(c[3])
        : "r"(a[0]), "r"(a[1]), "r"(a[2]), "r"(a[3]), "r"(b0), "r"(b1));
}

__global__ __launch_bounds__(256) void gemm_tc_kernel(
    const float* __restrict__ ego,
    const float* __restrict__ W1, const float* __restrict__ b1,
    const float* __restrict__ W2, const float* __restrict__ b2,
    float* __restrict__ out)
{
    __shared__ uint32_t sX1[BM][BK + XPAD];
    __shared__ uint32_t sX2[BM][BK + XPAD];
    __shared__ uint32_t sW1[BK][BN + WPAD];
    __shared__ uint32_t sW2[BK][BN + WPAD];

    const int t      = threadIdx.x;
    const int lane   = t & 31;
    const int wid    = t >> 5;
    const int warp_m = wid & 1;         // 0..1 (64-row band)
    const int warp_n = wid >> 1;        // 0..3 (32-col band)
    const int row0   = blockIdx.y * BM;
    const int col0   = blockIdx.x * BN;
    const int tg     = lane & 3;        // threadID in group
    const int gid    = lane >> 2;       // groupID

    float c1[4][4][4] = {};
    float c2[4][4][4] = {};

    const int xrow = t >> 2;            // 0..63
    const int xk4  = (t & 3) * 4;       // 0,4,8,12
    float4 pe[2], ps[2], pw1[2], pw2[2];

    auto load_tiles = [&](int k0) {
#pragma unroll
        for (int p = 0; p < 2; p++) {
            int grow = row0 + p * 64 + xrow;
            if (grow < N_NODES) {
                size_t off4 = ((size_t)grow * D + k0 + xk4) >> 2;
                pe[p] = __ldg(reinterpret_cast<const float4*>(ego) + off4);
                ps[p] = *(reinterpret_cast<const float4*>(g_side) + off4);
            } else {
                pe[p] = make_float4(0.f, 0.f, 0.f, 0.f);
                ps[p] = make_float4(0.f, 0.f, 0.f, 0.f);
            }
        }
#pragma unroll
        for (int i = 0; i < 2; i++) {
            int slot = t + i * 256;     // 0..511
            int wk   = slot >> 5;       // 0..15
            int c4   = (slot & 31) * 4; // 0..124
            size_t off4 = ((size_t)(k0 + wk) * D + col0 + c4) >> 2;
            pw1[i] = __ldg(reinterpret_cast<const float4*>(W1) + off4);
            pw2[i] = __ldg(reinterpret_cast<const float4*>(W2) + off4);
        }
    };

    auto store_tiles = [&]() {
#pragma unroll
        for (int p = 0; p < 2; p++) {
            int r = p * 64 + xrow;
            const float* e = &pe[p].x;
            const float* s = &ps[p].x;
#pragma unroll
            for (int j = 0; j < 4; j++) {
                sX1[r][xk4 + j] = f2tf32(e[j] + s[j]);
                sX2[r][xk4 + j] = f2tf32(e[j] * s[j]);
            }
        }
#pragma unroll
        for (int i = 0; i < 2; i++) {
            int slot = t + i * 256;
            int wk   = slot >> 5;
            int c4   = (slot & 31) * 4;
            const float* w1 = &pw1[i].x;
            const float* w2 = &pw2[i].x;
#pragma unroll
            for (int j = 0; j < 4; j++) {
                sW1[wk][c4 + j] = f2tf32(w1[j]);
                sW2[wk][c4 + j] = f2tf32(w2[j]);
            }
        }
    };

    load_tiles(0);

    const int NITER = D / BK;           // 16
    for (int it = 0; it < NITER; it++) {
        store_tiles();
        __syncthreads();
        if (it + 1 < NITER) load_tiles((it + 1) * BK);

#pragma unroll
        for (int ks = 0; ks < 2; ks++) {
            const int k8 = ks * 8;
            // --- GEMM 1 ---
            {
                uint32_t a[4][4];
#pragma unroll
                for (int mt = 0; mt < 4; mt++) {
                    int r = warp_m * 64 + mt * 16 + gid;
                    int c = k8 + tg;
                    a[mt][0] = sX1[r][c];
                    a[mt][1] = sX1[r + 8][c];
                    a[mt][2] = sX1[r][c + 4];
                    a[mt][3] = sX1[r + 8][c + 4];
                }
#pragma unroll
                for (int nt = 0; nt < 4; nt++) {
                    int n = warp_n * 32 + nt * 8 + gid;
                    int k = k8 + tg;
                    uint32_t b0 = sW1[k][n];
                    uint32_t b1v = sW1[k + 4][n];
#pragma unroll
                    for (int mt = 0; mt < 4; mt++)
                        mma_tf32(c1[mt][nt], a[mt], b0, b1v);
                }
            }
            // --- GEMM 2 ---
            {
                uint32_t a[4][4];
#pragma unroll
                for (int mt = 0; mt < 4; mt++) {
                    int r = warp_m * 64 + mt * 16 + gid;
                    int c = k8 + tg;
                    a[mt][0] = sX2[r][c];
                    a[mt][1] = sX2[r + 8][c];
                    a[mt][2] = sX2[r][c + 4];
                    a[mt][3] = sX2[r + 8][c + 4];
                }
#pragma unroll
                for (int nt = 0; nt < 4; nt++) {
                    int n = warp_n * 32 + nt * 8 + gid;
                    int k = k8 + tg;
                    uint32_t b0 = sW2[k][n];
                    uint32_t b1v = sW2[k + 4][n];
#pragma unroll
                    for (int mt = 0; mt < 4; mt++)
                        mma_tf32(c2[mt][nt], a[mt], b0, b1v);
                }
            }
        }
        __syncthreads();
    }

    // ----- epilogue: bias + LeakyReLU + sum -----
#pragma unroll
    for (int nt = 0; nt < 4; nt++) {
        int col = col0 + warp_n * 32 + nt * 8 + 2 * tg;
        float bb1_0 = __ldg(b1 + col),     bb1_1 = __ldg(b1 + col + 1);
        float bb2_0 = __ldg(b2 + col),     bb2_1 = __ldg(b2 + col + 1);
#pragma unroll
        for (int mt = 0; mt < 4; mt++) {
            int r = row0 + warp_m * 64 + mt * 16 + gid;
            float* cc1 = c1[mt][nt];
            float* cc2 = c2[mt][nt];
            if (r < N_NODES) {
                float o1a = cc1[0] + bb1_0; o1a = (o1a > 0.f) ? o1a : o1a * NEG_SLOPE;
                float o1b = cc1[1] + bb1_1; o1b = (o1b > 0.f) ? o1b : o1b * NEG_SLOPE;
                float o2a = cc2[0] + bb2_0; o2a = (o2a > 0.f) ? o2a : o2a * NEG_SLOPE;
                float o2b = cc2[1] + bb2_1; o2b = (o2b > 0.f) ? o2b : o2b * NEG_SLOPE;
                *reinterpret_cast<float2*>(out + (size_t)r * D + col) =
                    make_float2(o1a + o2a, o1b + o2b);
            }
            int r8 = r + 8;
            if (r8 < N_NODES) {
                float o1a = cc1[2] + bb1_0; o1a = (o1a > 0.f) ? o1a : o1a * NEG_SLOPE;
                float o1b = cc1[3] + bb1_1; o1b = (o1b > 0.f) ? o1b : o1b * NEG_SLOPE;
                float o2a = cc2[2] + bb2_0; o2a = (o2a > 0.f) ? o2a : o2a * NEG_SLOPE;
                float o2b = cc2[3] + bb2_1; o2b = (o2b > 0.f) ? o2b : o2b * NEG_SLOPE;
                *reinterpret_cast<float2*>(out + (size_t)r8 * D + col) =
                    make_float2(o1a + o2a, o1b + o2b);
            }
        }
    }
}

// ---------------------------------------------------------------------------
// Launch. Input order: 0 ego, 1 vals, 2 W1, 3 b1, 4 W2, 5 b2, 6 rows, 7 cols
// ---------------------------------------------------------------------------
extern "C" void kernel_launch(void* const* d_in, const int* in_sizes, int n_in,
                              void* d_out, int out_size)
{
    const float* ego  = (const float*)d_in[0];
    const float* vals = (const float*)d_in[1];
    const float* W1   = (const float*)d_in[2];
    const float* b1   = (const float*)d_in[3];
    const float* W2   = (const float*)d_in[4];
    const float* b2   = (const float*)d_in[5];
    const int*   rows = (const int*)d_in[6];
    const int*   cols = (const int*)d_in[7];
    float*       out  = (float*)d_out;

    zero_counts_kernel<<<(N_NODES + 255) / 256, 256>>>();
    hist_kernel<<<(E_EDGES + 255) / 256, 256>>>(rows);
    scan_kernel<<<1, SCAN_T>>>();
    fill_kernel<<<(E_EDGES + 255) / 256, 256>>>(rows, cols, vals);
    {
        long long threads = (long long)N_NODES * 32;
        int blocks = (int)((threads + 255) / 256);
        spmm_half_kernel<<<blocks, 256>>>(ego, 0);   // features 0..127
        spmm_half_kernel<<<blocks, 256>>>(ego, 32);  // features 128..255
    }
    {
        dim3 grid(D / BN, (N_NODES + BM - 1) / BM);  // (2, 782)
        gemm_tc_kernel<<<grid, 256>>>(ego, W1, b1, W2, b2, out);
    }
}